// round 5
// baseline (speedup 1.0000x reference)
#include <cuda_runtime.h>
#include <cstdint>

#define BB 8
#define CC 32
#define FF 8
#define HH 128
#define WW 128
#define IHP 129
#define IWP 132                       // padded row stride (floats), 528 B
typedef unsigned long long ull;

#define A_SMEM_FLOATS (IHP*IWP + 16*IWP)   // 76560 B

// Global integral scratch: (256, 129, 132) f32 = 17.4 MB (L2-resident)
__device__ __align__(256) float g_I[BB * CC * IHP * IWP];

// ---------------------------------------------------------------------------
// Kernel A: build padded integral image per (b,c) in smem, write to g_I.
// ---------------------------------------------------------------------------
__global__ void __launch_bounds__(512) build_integral(const float* __restrict__ in)
{
    extern __shared__ float sm[];
    float* I = sm;                      // [IHP][IWP]
    float* O = sm + IHP * IWP;          // [16][IWP] stripe offsets

    const int bc   = blockIdx.x;
    const int tid  = threadIdx.x;
    const int wid  = tid >> 5;
    const int lane = tid & 31;

    if (tid < IWP) I[tid] = 0.0f;

    const float* img = in + (size_t)bc * (HH * WW);
#pragma unroll
    for (int r = 0; r < 8; ++r) {
        int row = wid * 8 + r;
        float4 c = *(const float4*)(img + (size_t)row * WW + 4 * lane);
        float s4 = c.x + c.y + c.z + c.w;
        float x = __shfl_up_sync(0xffffffffu, s4, 1);
        if (lane == 0) x = 0.0f;
#pragma unroll
        for (int off = 1; off < 32; off <<= 1) {
            float t = __shfl_up_sync(0xffffffffu, x, off);
            if (lane >= off) x += t;
        }
        float4 o;
        o.x = x;
        o.y = x + c.x;
        o.z = o.y + c.y;
        o.w = o.z + c.z;
        float* dst = I + (size_t)(row + 1) * IWP;
        *(float4*)(dst + 4 * lane) = o;
        if (lane == 31) {
            dst[128] = o.w + c.w;
            dst[129] = 0.0f; dst[130] = 0.0f; dst[131] = 0.0f;
        }
    }
    __syncthreads();

    // level 1: within-stripe inclusive sums (8-row stripes)
    for (int g = lane; g < 33; g += 32) {
        float* col = I + 4 * g + (size_t)(8 * wid + 1) * IWP;
        float4 s = make_float4(0.f, 0.f, 0.f, 0.f);
#pragma unroll
        for (int r = 0; r < 8; ++r) {
            float4 v = *(float4*)(col + (size_t)r * IWP);
            s.x += v.x; s.y += v.y; s.z += v.z; s.w += v.w;
            *(float4*)(col + (size_t)r * IWP) = s;
        }
    }
    __syncthreads();

    // level 2: exclusive prefix of stripe totals
    if (tid < IWP) {
        float off = 0.0f;
        float* col = I + tid;
        float* ocol = O + tid;
#pragma unroll
        for (int s = 0; s < 16; ++s) {
            ocol[s * IWP] = off;
            off += col[(size_t)(8 * s + 8) * IWP];
        }
    }
    __syncthreads();

    // level 3: add stripe offsets
    for (int g = lane; g < 33; g += 32) {
        float4 o4 = *(float4*)(O + wid * IWP + 4 * g);
        float* col = I + 4 * g + (size_t)(8 * wid + 1) * IWP;
#pragma unroll
        for (int r = 0; r < 8; ++r) {
            float4 v = *(float4*)(col + (size_t)r * IWP);
            v.x += o4.x; v.y += o4.y; v.z += o4.z; v.w += o4.w;
            *(float4*)(col + (size_t)r * IWP) = v;
        }
    }
    __syncthreads();

    float4* dst = (float4*)(g_I + (size_t)bc * (IHP * IWP));
    const float4* src = (const float4*)I;
    const int n4 = (IHP * IWP) / 4;
    for (int i = tid; i < n4; i += 512) dst[i] = src[i];
}

// ---------------------------------------------------------------------------
// Helpers: packed f32x2 ops + 32-bit smem addressing
// ---------------------------------------------------------------------------
__device__ __forceinline__ ull pk2(float lo, float hi) {
    ull r; asm("mov.b64 %0, {%1, %2};" : "=l"(r) : "f"(lo), "f"(hi)); return r;
}
__device__ __forceinline__ ull ffma2(ull a, ull b, ull c) {
    ull r; asm("fma.rn.f32x2 %0, %1, %2, %3;" : "=l"(r) : "l"(a), "l"(b), "l"(c));
    return r;
}
__device__ __forceinline__ uint32_t smem_u32(const void* p) {
    uint32_t a;
    asm("{ .reg .u64 t; cvta.to.shared.u64 t, %1; cvt.u32.u64 %0, t; }"
        : "=r"(a) : "l"(p));
    return a;
}

// ---------------------------------------------------------------------------
// Kernel B: block = (quarter, bc), 8 warps = f. No smem integral: rolling
// window rows loaded straight from g_I (L2). D double-buffered per warp.
// ---------------------------------------------------------------------------
__global__ void __launch_bounds__(256, 5) boxconv_main(
    const float* __restrict__ xmn, const float* __restrict__ xmx,
    const float* __restrict__ ymn, const float* __restrict__ ymx,
    float* __restrict__ out)
{
    __shared__ float Dsh[8][2][IWP];      // 8448 B

    const int quarter = blockIdx.x;
    const int bc   = blockIdx.y;
    const int tid  = threadIdx.x;
    const int wid  = tid >> 5;
    const int lane = tid & 31;
    const int f    = wid;
    const int cf   = (bc % CC) * FF + f;

    const float Hf = 128.0f, Wf = 128.0f;
    const float xm = __ldg(&xmn[cf]) * Hf;
    const float xM = __ldg(&xmx[cf]) * Hf;
    const float ym = __ldg(&ymn[cf]) * Wf;
    const float yM = __ldg(&ymx[cf]) * Wf;

    // h-invariant column-interp params + fixed gather addresses
    const uint32_t dbase = smem_u32(&Dsh[wid][0][0]);
    uint32_t ga0[4], ga1[4];
    float b0[4], b1[4];
#pragma unroll
    for (int k = 0; k < 4; ++k) {
        float wv = (float)(lane + 32 * k);
        float v0 = fminf(fmaxf(wv + ym, 0.0f), Wf);
        float v1 = fminf(fmaxf(wv + yM + 1.0f, 0.0f), Wf);
        float j0f = fminf(floorf(v0), Wf - 1.0f);
        float j1f = fminf(floorf(v1), Wf - 1.0f);
        b0[k] = v0 - j0f;
        b1[k] = v1 - j1f;
        ga0[k] = dbase + 4u * (uint32_t)(int)j0f;
        ga1[k] = dbase + 4u * (uint32_t)(int)j1f;
    }

    const float* gIb = g_I + (size_t)bc * (IHP * IWP);
    float* outc = out + ((size_t)(bc * FF + f) * HH + quarter * 32) * WW + lane;

    const ull M1 = pk2(-1.0f, -1.0f);
    const uint32_t dst0 = dbase + 16u * (uint32_t)lane;

    // rolling window: rows i0, i0+1, i1, i1+1 (packed f32x2 pairs + col-128)
    ull r00a, r00b, r01a, r01b, r10a, r10b, r11a, r11b;
    float e00 = 0.f, e01 = 0.f, e10 = 0.f, e11 = 0.f;
    int pi0 = -2, pi1 = -2;

    const int h0 = quarter * 32;

#define LOADROW(base, ra, rb, e)                                            \
    { float4 v_ = *(const float4*)((base) + 4 * lane);                      \
      ra = pk2(v_.x, v_.y); rb = pk2(v_.z, v_.w); e = __ldg((base) + 128); }

#define ITER(SUB, SOFF)                                                      \
    {                                                                        \
        const int h = h0 + hh + (SUB);                                       \
        float u0 = fminf(fmaxf((float)h + xm, 0.0f), Hf);                    \
        float u1 = fminf(fmaxf((float)h + xM + 1.0f, 0.0f), Hf);             \
        float i0f = fminf(floorf(u0), 127.0f);                               \
        float i1f = fminf(floorf(u1), 127.0f);                               \
        float a0 = u0 - i0f, a1 = u1 - i1f;                                  \
        int i0 = (int)i0f, i1 = (int)i1f;                                    \
        if (i0 != pi0) {                                                     \
            const float* base = gIb + (size_t)i0 * IWP;                      \
            if (i0 == pi0 + 1) { r00a = r01a; r00b = r01b; e00 = e01; }      \
            else LOADROW(base, r00a, r00b, e00);                             \
            LOADROW(base + IWP, r01a, r01b, e01);                            \
            pi0 = i0;                                                        \
        }                                                                    \
        if (i1 != pi1) {                                                     \
            const float* base = gIb + (size_t)i1 * IWP;                      \
            if (i1 == pi1 + 1) { r10a = r11a; r10b = r11b; e10 = e11; }      \
            else LOADROW(base, r10a, r10b, e10);                             \
            LOADROW(base + IWP, r11a, r11b, e11);                            \
            pi1 = i1;                                                        \
        }                                                                    \
        ull a0v = pk2(a0, a0), a1v = pk2(a1, a1);                            \
        ull g0a = ffma2(a0v, ffma2(r00a, M1, r01a), r00a);                   \
        ull g0b = ffma2(a0v, ffma2(r00b, M1, r01b), r00b);                   \
        ull g1a = ffma2(a1v, ffma2(r10a, M1, r11a), r10a);                   \
        ull g1b = ffma2(a1v, ffma2(r10b, M1, r11b), r10b);                   \
        ull da = ffma2(g0a, M1, g1a);                                        \
        ull db = ffma2(g0b, M1, g1b);                                        \
        asm volatile("st.shared.v2.u64 [%0+" #SOFF "], {%1, %2};"            \
                     :: "r"(dst0), "l"(da), "l"(db) : "memory");             \
        if (lane == 0) {                                                     \
            float ge0 = fmaf(a0, e01 - e00, e00);                            \
            float ge1 = fmaf(a1, e11 - e10, e10);                            \
            asm volatile("st.shared.f32 [%0+512+" #SOFF "], %1;"             \
                         :: "r"(dbase), "f"(ge1 - ge0) : "memory");          \
        }                                                                    \
        __syncwarp();                                                        \
        float* orow = outc + (size_t)(hh + (SUB)) * WW;                      \
        _Pragma("unroll")                                                    \
        for (int k = 0; k < 4; ++k) {                                        \
            float d00, d01, d10, d11;                                        \
            asm volatile("ld.shared.f32 %0, [%1+" #SOFF "];"                 \
                         : "=f"(d00) : "r"(ga0[k]));                         \
            asm volatile("ld.shared.f32 %0, [%1+4+" #SOFF "];"               \
                         : "=f"(d01) : "r"(ga0[k]));                         \
            asm volatile("ld.shared.f32 %0, [%1+" #SOFF "];"                 \
                         : "=f"(d10) : "r"(ga1[k]));                         \
            asm volatile("ld.shared.f32 %0, [%1+4+" #SOFF "];"               \
                         : "=f"(d11) : "r"(ga1[k]));                         \
            float s0 = fmaf(b0[k], d01 - d00, d00);                          \
            float s1 = fmaf(b1[k], d11 - d10, d10);                          \
            orow[32 * k] = s1 - s0;                                          \
        }                                                                    \
    }

    for (int hh = 0; hh < 32; hh += 2) {
        ITER(0, 0)
        ITER(1, 528)
    }
#undef ITER
#undef LOADROW
}

// ---------------------------------------------------------------------------
extern "C" void kernel_launch(void* const* d_in, const int* in_sizes, int n_in,
                              void* d_out, int out_size) {
    const float* input = (const float*)d_in[0];
    const float* x_min = (const float*)d_in[1];
    const float* x_max = (const float*)d_in[2];
    const float* y_min = (const float*)d_in[3];
    const float* y_max = (const float*)d_in[4];
    float* out = (float*)d_out;

    static int configured = 0;
    const int a_smem = A_SMEM_FLOATS * sizeof(float);   // 76560 B
    if (!configured) {
        cudaFuncSetAttribute(build_integral,
                             cudaFuncAttributeMaxDynamicSharedMemorySize, a_smem);
        configured = 1;
    }

    build_integral<<<BB * CC, 512, a_smem>>>(input);

    dim3 grid(4, BB * CC);    // (h-quarter, bc)
    boxconv_main<<<grid, 256>>>(x_min, x_max, y_min, y_max, out);
}

// round 6
// speedup vs baseline: 1.4511x; 1.4511x over previous
#include <cuda_runtime.h>
#include <cstdint>

#define BB 8
#define CC 32
#define FF 8
#define HH 128
#define WW 128
#define IHP 129
#define IWP 132                        // padded row stride (floats), 528 B
typedef unsigned long long ull;

// smem layout (floats):
#define T_OFF (IHP*IWP)                // 17028 : T table, 1024 float4 = 4096 f
#define D_OFF (T_OFF + 4096)           // 21124 : D buffers 16 warps * 264 f
                                       //         (also reused as build stripe offsets)
#define SMEM_FLOATS (D_OFF + 16*264)   // 25348 floats = 101392 B

__device__ __forceinline__ ull pk2(float lo, float hi) {
    ull r; asm("mov.b64 %0, {%1, %2};" : "=l"(r) : "f"(lo), "f"(hi)); return r;
}
__device__ __forceinline__ ull ffma2(ull a, ull b, ull c) {
    ull r; asm("fma.rn.f32x2 %0, %1, %2, %3;" : "=l"(r) : "l"(a), "l"(b), "l"(c));
    return r;
}
__device__ __forceinline__ uint32_t smem_u32(const void* p) {
    uint32_t a;
    asm("{ .reg .u64 t; cvta.to.shared.u64 t, %1; cvt.u32.u64 %0, t; }"
        : "=r"(a) : "l"(p));
    return a;
}

// ---------------------------------------------------------------------------
// Fused: one block per bc. Build integral + T table, then 16 warps = (f, half)
// each produce 64 output rows with a rolling register window over I.
// ---------------------------------------------------------------------------
__global__ void __launch_bounds__(512, 2) boxconv_fused(
    const float* __restrict__ in,
    const float* __restrict__ xmn, const float* __restrict__ xmx,
    const float* __restrict__ ymn, const float* __restrict__ ymx,
    float* __restrict__ out)
{
    extern __shared__ float sm[];
    float*  I = sm;                                 // [IHP][IWP]
    float4* T = (float4*)(sm + T_OFF);              // [FF*HH]
    float*  O = sm + D_OFF;                         // build stripe offsets (reuse)

    const int bc   = blockIdx.x;
    const int c    = bc % CC;
    const int tid  = threadIdx.x;
    const int wid  = tid >> 5;
    const int lane = tid & 31;

    // ---- T table: per (f,h) row offsets (bytes) + fractional weights -------
    for (int e = tid; e < FF * HH; e += 512) {
        int fi = e >> 7, h = e & 127;
        int cfi = c * FF + fi;
        float xm = xmn[cfi] * 128.0f;
        float xM = xmx[cfi] * 128.0f;
        float u0 = fminf(fmaxf((float)h + xm, 0.0f), 128.0f);
        float u1 = fminf(fmaxf((float)h + xM + 1.0f, 0.0f), 128.0f);
        int i0 = min(max(h + (int)floorf(xm), 0), 127);
        int i1 = min(max(h + (int)floorf(xM + 1.0f), 0), 127);
        float4 t;
        t.x = __int_as_float(i0 * (IWP * 4));
        t.y = __int_as_float(i1 * (IWP * 4));
        t.z = u0 - (float)i0;
        t.w = u1 - (float)i1;
        T[e] = t;
    }

    // ---- Build I: row scans (warp wid -> rows 8w..8w+7) --------------------
    if (tid < IWP) I[tid] = 0.0f;
    const float* img = in + (size_t)bc * (HH * WW);
#pragma unroll
    for (int r = 0; r < 8; ++r) {
        int row = wid * 8 + r;
        float4 cv = *(const float4*)(img + (size_t)row * WW + 4 * lane);
        float s4 = cv.x + cv.y + cv.z + cv.w;
        float x = __shfl_up_sync(0xffffffffu, s4, 1);
        if (lane == 0) x = 0.0f;
#pragma unroll
        for (int off = 1; off < 32; off <<= 1) {
            float t = __shfl_up_sync(0xffffffffu, x, off);
            if (lane >= off) x += t;
        }
        float4 o;
        o.x = x;
        o.y = x + cv.x;
        o.z = o.y + cv.y;
        o.w = o.z + cv.z;
        float* dst = I + (size_t)(row + 1) * IWP;
        *(float4*)(dst + 4 * lane) = o;
        if (lane == 31) {
            dst[128] = o.w + cv.w;
            dst[129] = 0.0f; dst[130] = 0.0f; dst[131] = 0.0f;
        }
    }
    __syncthreads();

    // level 1: within-stripe inclusive sums (8-row stripes)
    for (int g = lane; g < 33; g += 32) {
        float* col = I + 4 * g + (size_t)(8 * wid + 1) * IWP;
        float4 s = make_float4(0.f, 0.f, 0.f, 0.f);
#pragma unroll
        for (int r = 0; r < 8; ++r) {
            float4 v = *(float4*)(col + (size_t)r * IWP);
            s.x += v.x; s.y += v.y; s.z += v.z; s.w += v.w;
            *(float4*)(col + (size_t)r * IWP) = s;
        }
    }
    __syncthreads();

    // level 2: exclusive prefix of stripe totals (into O)
    if (tid < IWP) {
        float off = 0.0f;
        float* col = I + tid;
        float* ocol = O + tid;
#pragma unroll
        for (int s = 0; s < 16; ++s) {
            ocol[s * IWP] = off;
            off += col[(size_t)(8 * s + 8) * IWP];
        }
    }
    __syncthreads();

    // level 3: add stripe offsets
    for (int g = lane; g < 33; g += 32) {
        float4 o4 = *(float4*)(O + wid * IWP + 4 * g);
        float* col = I + 4 * g + (size_t)(8 * wid + 1) * IWP;
#pragma unroll
        for (int r = 0; r < 8; ++r) {
            float4 v = *(float4*)(col + (size_t)r * IWP);
            v.x += o4.x; v.y += o4.y; v.z += o4.z; v.w += o4.w;
            *(float4*)(col + (size_t)r * IWP) = v;
        }
    }
    __syncthreads();

    // ---- Phase C: warp = (f, half) ------------------------------------------
    const int f    = wid & 7;
    const int half = wid >> 3;
    const int cf   = c * FF + f;
    const float Wf = 128.0f;

    const float ym = __ldg(&ymn[cf]) * Wf;
    const float yM = __ldg(&ymx[cf]) * Wf;

    const uint32_t dbase = smem_u32(sm + D_OFF + wid * 264);
    uint32_t ga0[4], ga1[4];
    float b0[4], b1[4];
#pragma unroll
    for (int k = 0; k < 4; ++k) {
        float wv = (float)(lane + 32 * k);
        float v0 = fminf(fmaxf(wv + ym, 0.0f), Wf);
        float v1 = fminf(fmaxf(wv + yM + 1.0f, 0.0f), Wf);
        float j0f = fminf(floorf(v0), Wf - 1.0f);
        float j1f = fminf(floorf(v1), Wf - 1.0f);
        b0[k] = v0 - j0f;
        b1[k] = v1 - j1f;
        ga0[k] = dbase + 4u * (uint32_t)(int)j0f;
        ga1[k] = dbase + 4u * (uint32_t)(int)j1f;
    }

    const char* smb = (const char*)sm;
    const ull M1 = pk2(-1.0f, -1.0f);
    const uint32_t dst0 = dbase + 16u * (uint32_t)lane;
    float* outc = out + ((size_t)(bc * FF + f) * HH + half * 64) * WW + lane;
    const float4* Tw = T + (f << 7) + half * 64;

    ull r00a, r00b, r01a, r01b, r10a, r10b, r11a, r11b;
    float e00 = 0.f, e01 = 0.f, e10 = 0.f, e11 = 0.f;
    int po0 = -1000000, po1 = -1000000;

#define LOADROW(BOFF, ra, rb, e)                                             \
    { float4 v_ = *(const float4*)(smb + (BOFF) + 16 * lane);                \
      ra = pk2(v_.x, v_.y); rb = pk2(v_.z, v_.w);                            \
      e = *(const float*)(smb + (BOFF) + 512); }

#define ITER(SUB, SOFF)                                                      \
    {                                                                        \
        float4 tv = Tw[hh + (SUB)];                                          \
        int off0 = __float_as_int(tv.x);                                     \
        int off1 = __float_as_int(tv.y);                                     \
        float a0 = tv.z, a1 = tv.w;                                          \
        if (off0 != po0) {                                                   \
            if (off0 == po0 + 528) { r00a = r01a; r00b = r01b; e00 = e01; }  \
            else LOADROW(off0, r00a, r00b, e00);                             \
            LOADROW(off0 + 528, r01a, r01b, e01);                            \
            po0 = off0;                                                      \
        }                                                                    \
        if (off1 != po1) {                                                   \
            if (off1 == po1 + 528) { r10a = r11a; r10b = r11b; e10 = e11; }  \
            else LOADROW(off1, r10a, r10b, e10);                             \
            LOADROW(off1 + 528, r11a, r11b, e11);                            \
            po1 = off1;                                                      \
        }                                                                    \
        ull a0v = pk2(a0, a0), a1v = pk2(a1, a1);                            \
        ull g0a = ffma2(a0v, ffma2(r00a, M1, r01a), r00a);                   \
        ull g0b = ffma2(a0v, ffma2(r00b, M1, r01b), r00b);                   \
        ull g1a = ffma2(a1v, ffma2(r10a, M1, r11a), r10a);                   \
        ull g1b = ffma2(a1v, ffma2(r10b, M1, r11b), r10b);                   \
        ull da = ffma2(g0a, M1, g1a);                                        \
        ull db = ffma2(g0b, M1, g1b);                                        \
        asm volatile("st.shared.v2.u64 [%0+" #SOFF "], {%1, %2};"            \
                     :: "r"(dst0), "l"(da), "l"(db) : "memory");             \
        float ge0 = fmaf(a0, e01 - e00, e00);                                \
        float ge1 = fmaf(a1, e11 - e10, e10);                                \
        if (lane == 0)                                                       \
            asm volatile("st.shared.f32 [%0+512+" #SOFF "], %1;"             \
                         :: "r"(dbase), "f"(ge1 - ge0) : "memory");          \
        __syncwarp();                                                        \
        float* orow = outc + (size_t)(hh + (SUB)) * WW;                      \
        _Pragma("unroll")                                                    \
        for (int k = 0; k < 4; ++k) {                                        \
            float d00, d01, d10, d11;                                        \
            asm volatile("ld.shared.f32 %0, [%1+" #SOFF "];"                 \
                         : "=f"(d00) : "r"(ga0[k]));                         \
            asm volatile("ld.shared.f32 %0, [%1+4+" #SOFF "];"               \
                         : "=f"(d01) : "r"(ga0[k]));                         \
            asm volatile("ld.shared.f32 %0, [%1+" #SOFF "];"                 \
                         : "=f"(d10) : "r"(ga1[k]));                         \
            asm volatile("ld.shared.f32 %0, [%1+4+" #SOFF "];"               \
                         : "=f"(d11) : "r"(ga1[k]));                         \
            float s0 = fmaf(b0[k], d01 - d00, d00);                          \
            float s1 = fmaf(b1[k], d11 - d10, d10);                          \
            orow[32 * k] = s1 - s0;                                          \
        }                                                                    \
    }

    for (int hh = 0; hh < 64; hh += 2) {
        ITER(0, 0)
        ITER(1, 528)
    }
#undef ITER
#undef LOADROW
}

// ---------------------------------------------------------------------------
extern "C" void kernel_launch(void* const* d_in, const int* in_sizes, int n_in,
                              void* d_out, int out_size) {
    const float* input = (const float*)d_in[0];
    const float* x_min = (const float*)d_in[1];
    const float* x_max = (const float*)d_in[2];
    const float* y_min = (const float*)d_in[3];
    const float* y_max = (const float*)d_in[4];
    float* out = (float*)d_out;

    static int configured = 0;
    const int smem_bytes = SMEM_FLOATS * sizeof(float);   // 101392 B
    if (!configured) {
        cudaFuncSetAttribute(boxconv_fused,
                             cudaFuncAttributeMaxDynamicSharedMemorySize,
                             smem_bytes);
        configured = 1;
    }

    boxconv_fused<<<BB * CC, 512, smem_bytes>>>(
        input, x_min, x_max, y_min, y_max, out);
}